// round 10
// baseline (speedup 1.0000x reference)
#include <cuda_runtime.h>

// Shapes fixed by dataset: b=8, n=1024, m=2048, x_dim=1, c=3, Z=128
#define BB     8
#define NN     1024
#define MM     2048
#define MTB    64          // m-rows per block
#define NCTR   12          // Hermite centers, c_l = l - 5.5, spacing 1
#define KH     13          // Hermite terms k = 0..12
#define BCAP   640         // bucket capacity (mean ~350, +19 sigma margin)
#define EPSV   1e-8f
#define LOG2E  1.4426950408889634f
#define K2     (-0.5f * LOG2E)   // exp(-u^2/2) = exp2(K2*u^2)

__device__ __forceinline__ float ex2f(float v) {
    float r;
    asm("ex2.approx.ftz.f32 %0, %1;" : "=f"(r) : "f"(v));
    return r;
}

// ---------------------------------------------------------------------------
// Fused kernel: 256 blocks x 384 threads (12 warps). Warp = Hermite center.
//  (a) stage scaled x', y in smem
//  (b) deterministic ballot-compaction bucketing (no atomics)
//  (c) per-warp moment accumulation over ITS bucket only (dense, no divergence)
//  (d) shfl butterfly -> all lanes hold the 39 moments in registers
//  (e) Hermite evaluation per m-row, combine, normalize, project, store
// ---------------------------------------------------------------------------
__global__ __launch_bounds__(384)
void enc_fused(const float* __restrict__ x,
               const float* __restrict__ y,
               const float* __restrict__ t,
               const float* __restrict__ sigma,
               const float* __restrict__ W,
               const float* __restrict__ bfc,
               float* __restrict__ out)
{
    __shared__ float  sxp[NN];                 //  4 KB scaled x'
    __shared__ float2 sy[NN];                  //  8 KB y pairs
    __shared__ unsigned short bidx[NCTR][BCAP];// 15 KB bucket index lists
    __shared__ float4 red[NCTR][MTB];          // 12 KB per-center partials
    __shared__ float4 zfin[MTB];               //  1 KB
    __shared__ float4 sW[96];                  //  1.5 KB
    __shared__ float4 sB[32];                  //  0.5 KB

    const int tid  = threadIdx.x;
    const int lane = tid & 31;
    const int wrp  = tid >> 5;          // 0..11 = center (fast) / n-slice (fallback)
    const int blk  = blockIdx.x;
    const int b    = blk >> 5;          // 32 m-tiles per batch
    const int m_base = (blk & 31) * MTB;

    const float C0 = -0.5f * LOG2E * __expf(-2.f * sigma[0]);
    const float C1 = -0.5f * LOG2E * __expf(-2.f * sigma[1]);
    const float C2 = -0.5f * LOG2E * __expf(-2.f * sigma[2]);
    const float s  = __expf(sigma[0]);
    const bool fast = (C0 == C1) && (C0 == C2) && (s >= 0.8f) && (s <= 1.25f);

    // Stage W + bias (both paths need them)
    if (tid < 96)  sW[tid] = reinterpret_cast<const float4*>(W)[tid];
    if (tid >= 96 && tid < 128) sB[tid - 96] = reinterpret_cast<const float4*>(bfc)[tid - 96];

    if (fast) {
        const float s_inv = 1.f / s;
        // (a) stage scaled x' and y
        {
            const float*  xb = x + b * NN;
            const float2* yb = reinterpret_cast<const float2*>(y + b * NN * 2);
            for (int i = tid; i < NN; i += 384) {
                sxp[i] = __ldg(xb + i) * s_inv;
                sy[i]  = __ldg(yb + i);
            }
        }
        __syncthreads();

        // (b) deterministic compaction: warp w collects its bucket's indices
        int cnt = 0;
        #pragma unroll 4
        for (int cb = 0; cb < NN; cb += 32) {
            float xv = sxp[cb + lane];
            int l = (int)floorf(xv + 6.0f);
            l = min(max(l, 0), NCTR - 1);
            unsigned mask = __ballot_sync(0xffffffffu, l == wrp);
            if (l == wrp) {
                int rank = __popc(mask & ((1u << lane) - 1u));
                int pos  = cnt + rank;
                if (pos < BCAP) bidx[wrp][pos] = (unsigned short)(cb + lane);
            }
            cnt += __popc(mask);
        }
        if (cnt > BCAP) cnt = BCAP;

        // (c) moments over this warp's bucket only (dense iterations)
        const float c = (float)wrp - 5.5f;
        const float INVK[KH] = {0.f, 1.f, 0.5f, 1.f/3.f, 0.25f, 0.2f, 1.f/6.f,
                                1.f/7.f, 0.125f, 1.f/9.f, 0.1f, 1.f/11.f, 1.f/12.f};
        float a0[KH], a1[KH], a2[KH];
        #pragma unroll
        for (int k = 0; k < KH; ++k) { a0[k] = 0.f; a1[k] = 0.f; a2[k] = 0.f; }

        for (int j = lane; j < cnt; j += 32) {
            int i = bidx[wrp][j];
            float  w_ = sxp[i] - c;
            float2 yv = sy[i];
            float p = 1.f;
            a0[0] += 1.f; a1[0] += yv.x; a2[0] += yv.y;
            #pragma unroll
            for (int k = 1; k < KH; ++k) {
                p = p * w_ * INVK[k];
                a0[k] += p;
                a1[k] = fmaf(p, yv.x, a1[k]);
                a2[k] = fmaf(p, yv.y, a2[k]);
            }
        }

        // (d) butterfly: all lanes end with the full 39 moments
        #pragma unroll
        for (int off = 16; off; off >>= 1) {
            #pragma unroll
            for (int k = 0; k < KH; ++k) {
                a0[k] += __shfl_xor_sync(0xffffffffu, a0[k], off);
                a1[k] += __shfl_xor_sync(0xffffffffu, a1[k], off);
                a2[k] += __shfl_xor_sync(0xffffffffu, a2[k], off);
            }
        }

        // (e) Hermite evaluation: lane = m-row, two row groups of 32
        #pragma unroll
        for (int rg = 0; rg < 2; ++rg) {
            const int row = rg * 32 + lane;
            const float tr = __ldg(t + b * MM + m_base + row) * s_inv;
            const float u  = tr - c;
            const float E  = ex2f(K2 * u * u);

            float Hk2 = E;                    // He_0 * E
            float s0 = a0[0] * Hk2;
            float s1 = a1[0] * Hk2;
            float s2 = a2[0] * Hk2;
            float Hk1 = u * E;                // He_1 * E
            s0 = fmaf(a0[1], Hk1, s0);
            s1 = fmaf(a1[1], Hk1, s1);
            s2 = fmaf(a2[1], Hk1, s2);
            #pragma unroll
            for (int k = 2; k < KH; ++k) {
                float Hk = fmaf(u, Hk1, -(float)(k - 1) * Hk2);  // He recurrence * E
                s0 = fmaf(a0[k], Hk, s0);
                s1 = fmaf(a1[k], Hk, s1);
                s2 = fmaf(a2[k], Hk, s2);
                Hk2 = Hk1; Hk1 = Hk;
            }
            red[wrp][row] = make_float4(s0, s1, s2, 0.f);
        }
    } else {
        // Exact direct fallback: warp wrp scans its n-slice for all 64 rows
        __syncthreads();   // match fast-path sync count (branch is block-uniform)
        const int nstart = wrp * 86;
        const int nend   = min(NN, nstart + 86);
        const float*  xb = x + b * NN;
        const float2* yb = reinterpret_cast<const float2*>(y + b * NN * 2);
        #pragma unroll
        for (int rg = 0; rg < 2; ++rg) {
            const int row = rg * 32 + lane;
            const float tr = __ldg(t + b * MM + m_base + row);
            float s0 = 0.f, s1 = 0.f, s2 = 0.f;
            for (int i = nstart; i < nend; ++i) {
                float  d  = tr - __ldg(xb + i);
                float2 yv = __ldg(yb + i);
                float d2 = d * d;
                float e0 = ex2f(C0 * d2);
                float e1 = ex2f(C1 * d2);
                float e2 = ex2f(C2 * d2);
                s0 += e0;
                s1 = fmaf(e1, yv.x, s1);
                s2 = fmaf(e2, yv.y, s2);
            }
            red[wrp][row] = make_float4(s0, s1, s2, 0.f);
        }
    }
    __syncthreads();

    // Combine 12 center/slice partials per row, normalize
    if (tid < MTB) {
        float d0 = 0.f, d1 = 0.f, d2 = 0.f;
        #pragma unroll
        for (int wdx = 0; wdx < NCTR; ++wdx) {
            float4 p = red[wdx][tid];
            d0 += p.x; d1 += p.y; d2 += p.z;
        }
        float inv = 1.f / (d0 + EPSV);
        zfin[tid] = make_float4(d0, d1 * inv, d2 * inv, 0.f);
    }
    __syncthreads();

    // Epilogue: 64 rows x 32 col-groups = 2048 float4 stores over 384 threads
    float4* out4 = reinterpret_cast<float4*>(out);
    const size_t rowbase = (size_t)(b * MM + m_base);
    for (int j = tid; j < MTB * 32; j += 384) {
        const int row = j >> 5;
        const int k4  = j & 31;
        const float4 z  = zfin[row];
        const float4 wa = sW[3 * k4];
        const float4 wb = sW[3 * k4 + 1];
        const float4 wc = sW[3 * k4 + 2];
        const float4 bb = sB[k4];
        float4 o;
        o.x = fmaf(z.x, wa.x, fmaf(z.y, wa.y, fmaf(z.z, wa.z, bb.x)));
        o.y = fmaf(z.x, wa.w, fmaf(z.y, wb.x, fmaf(z.z, wb.y, bb.y)));
        o.z = fmaf(z.x, wb.z, fmaf(z.y, wb.w, fmaf(z.z, wc.x, bb.z)));
        o.w = fmaf(z.x, wc.y, fmaf(z.y, wc.z, fmaf(z.z, wc.w, bb.w)));
        out4[(rowbase + row) * 32 + k4] = o;
    }
}

extern "C" void kernel_launch(void* const* d_in, const int* in_sizes, int n_in,
                              void* d_out, int out_size)
{
    const float* x     = (const float*)d_in[0];   // (8,1024,1)
    const float* y     = (const float*)d_in[1];   // (8,1024,2)
    const float* t     = (const float*)d_in[2];   // (8,2048,1)
    const float* sigma = (const float*)d_in[3];   // (3,)
    const float* W     = (const float*)d_in[4];   // (128,3)
    const float* bfc   = (const float*)d_in[5];   // (128,)
    float* out = (float*)d_out;                   // (8,2048,128)

    enc_fused<<<BB * (MM / MTB), 384>>>(x, y, t, sigma, W, bfc, out);
}